// round 8
// baseline (speedup 1.0000x reference)
#include <cuda_runtime.h>
#include <math.h>

#define NROWS 1024
#define C 64
#define MARGIN_F 15.0f
#define EPSJ 1e-8f
#define HLN2 0.34657359027997264f   /* 0.5*ln2 */

/* gram kernel tiling */
#define GTI 32
#define GTJ 64
/* js kernel tiling */
#define JTI 32
#define JTJ 32
#define NBLKJ 1024                   /* (1024/JTI)*(1024/JTJ) */

// ---------------- scratch (static device globals; no allocation) ----------------
__device__ float g_K[2][NROWS];      // 0.5*Sa + 0.5*ln2*sumA  per row
__device__ float g_nn[2][NROWS];     // ||x||^2 per row
__device__ float g_pos[2 * NROWS];   // per-row positive-branch contribution
__device__ float g_oodv[2 * NROWS];  // per-row ood contribution (var*coffi)
__device__ float g_rowsum[NROWS];    // negative-branch per-row pair sums
__device__ int   g_rowcnt[NROWS];    // negative-branch per-row counts
__device__ int   g_done;             // js-kernel completion counter
__device__ float g_w[NROWS][NROWS];  // per-pair weight hinge*(1-dl)  (4 MB)

__device__ __forceinline__ unsigned long long fma2(unsigned long long a,
                                                   unsigned long long b,
                                                   unsigned long long c) {
    unsigned long long d;
    asm("fma.rn.f32x2 %0, %1, %2, %3;" : "=l"(d) : "l"(a), "l"(b), "l"(c));
    return d;
}

union F4U {
    float4 f;
    unsigned long long u[2];
    float s[4];
};

__device__ __forceinline__ float wsum(float v) {
    #pragma unroll
    for (int off = 16; off; off >>= 1) v += __shfl_xor_sync(0xffffffffu, v, off);
    return v;
}
__device__ __forceinline__ float wmin(float v) {
    #pragma unroll
    for (int off = 16; off; off >>= 1)
        v = fminf(v, __shfl_xor_sync(0xffffffffu, v, off));
    return v;
}

// ---------------- kernel 1: warp-per-row precompute + positive + ood ------------
__global__ void row_kernel(const float* __restrict__ x1, const float* __restrict__ x2,
                           const float* __restrict__ xp1, const float* __restrict__ xp2,
                           const float* __restrict__ l1,  const float* __restrict__ l2) {
    int gtid = blockIdx.x * blockDim.x + threadIdx.x;
    int w    = gtid >> 5;            // warp id: 0..2047
    int lane = gtid & 31;
    if (gtid == 0) g_done = 0;
    if (gtid < NROWS) { g_rowsum[gtid] = 0.0f; g_rowcnt[gtid] = 0; }

    int br = w >> 10;
    int i  = w & (NROWS - 1);
    const float* xr = (br ? x2  : x1)  + i * C;
    const float* pr = (br ? xp2 : xp1) + i * C;
    const float* lr = (br ? l2  : l1)  + i * C;

    float xv0 = xr[lane], xv1 = xr[lane + 32];
    float A0  = pr[lane] + EPSJ, A1 = pr[lane + 32] + EPSJ;
    float lv0 = lr[lane], lv1 = lr[lane + 32];

    float nn = wsum(fmaf(xv0, xv0, xv1 * xv1));

    float la0 = __logf(A0),                 la1 = __logf(A1);
    float L00 = __logf(0.5f * (A0 + EPSJ)), L01 = __logf(0.5f * (A1 + EPSJ));
    float L10 = __logf(0.5f * (A0 + 1.0f)), L11 = __logf(0.5f * (A1 + 1.0f));
    float P  = fmaf(A0, la0 - L00, A1 * (la1 - L01));
    float T  = L00 + L01;
    float Sa = fmaf(A0, la0, A1 * la1);
    float sA = A0 + A1;

    float pd0 = sqrtf(fmaxf(nn - 2.0f * xv0 + 1.0f, 1e-12f));
    float pd1 = sqrtf(fmaxf(nn - 2.0f * xv1 + 1.0f, 1e-12f));
    float h0  = -0.5f * A0 * (L00 - L10) - 0.5f * EPSJ * L00 + 0.5f * L10;
    float h1  = -0.5f * A1 * (L01 - L11) - 0.5f * EPSJ * L01 + 0.5f * L11;
    float w0  = pd0 * lv0, w1 = pd1 * lv1;
    float S1  = w0 + w1;
    float S2  = fmaf(w0, h0, w1 * h1);
    float r0  = fmaxf(MARGIN_F - pd0, 0.0f) * (1.0f / MARGIN_F);
    float r1  = fmaxf(MARGIN_F - pd1, 0.0f) * (1.0f / MARGIN_F);
    float var = fmaf(r0, r0, r1 * r1);
    float mn  = fminf(1.0f - r0, 1.0f - r1);

    P = wsum(P); T = wsum(T); Sa = wsum(Sa); sA = wsum(sA);
    S1 = wsum(S1); S2 = wsum(S2); var = wsum(var); mn = wmin(mn);

    if (lane == 0) {
        const float LOGEPS = -18.420680743952367f;   // ln(1e-8)
        float G = 1.0f - 0.5f * P - 0.5f * EPSJ * (float)(C - 1) * LOGEPS
                       + 0.5f * EPSJ * T;
        g_pos [w]   = G * S1 + S2;
        g_oodv[w]   = var * mn;
        g_K [br][i] = 0.5f * Sa + HLN2 * sA;
        g_nn[br][i] = nn;
    }
}

// ---------------- kernel 2: gram + weights --------------------------------------
// 32i x 64j tile, 128 thr (16tx x 8ty), 4i x 4j micro-tile.
// dl/dx via packed f32x2 FMA; w = hinge*(1-dl) -> g_w (float4 STG, coalesced);
// per-row counts via width-16 shuffle + atomics (w>0 <=> pairs>0, js>0 strictly).
__global__ void __launch_bounds__(128, 4)
gram_kernel(const float* __restrict__ x1, const float* __restrict__ x2,
            const float* __restrict__ l1,  const float* __restrict__ l2) {
    extern __shared__ float sm[];
    float2* sPi = (float2*)sm;            // [C][GTI] (l1,x1)  16 KB
    float2* sPj = sPi + C * GTI;          // [C][GTJ] (l2,x2)  32 KB

    const int tx = threadIdx.x, ty = threadIdx.y;
    const int tid = ty * 16 + tx;
    const int i0 = blockIdx.y * GTI, j0 = blockIdx.x * GTJ;

    {
        int r = tid & 31, c0 = tid >> 5;          // c0: 0..3
        #pragma unroll
        for (int p = 0; p < 4; p++) {
            int cb = c0 + 4 * p;
            float4 lv = *(const float4*)&l1[(i0 + r) * C + cb * 4];
            float4 xv = *(const float4*)&x1[(i0 + r) * C + cb * 4];
            sPi[(cb * 4 + 0) * GTI + r] = make_float2(lv.x, xv.x);
            sPi[(cb * 4 + 1) * GTI + r] = make_float2(lv.y, xv.y);
            sPi[(cb * 4 + 2) * GTI + r] = make_float2(lv.z, xv.z);
            sPi[(cb * 4 + 3) * GTI + r] = make_float2(lv.w, xv.w);
        }
    }
    {
        int r = tid & 63, c0 = tid >> 6;          // c0: 0..1
        #pragma unroll
        for (int p = 0; p < 8; p++) {
            int cb = c0 + 2 * p;
            float4 lv = *(const float4*)&l2[(j0 + r) * C + cb * 4];
            float4 xv = *(const float4*)&x2[(j0 + r) * C + cb * 4];
            sPj[(cb * 4 + 0) * GTJ + r] = make_float2(lv.x, xv.x);
            sPj[(cb * 4 + 1) * GTJ + r] = make_float2(lv.y, xv.y);
            sPj[(cb * 4 + 2) * GTJ + r] = make_float2(lv.z, xv.z);
            sPj[(cb * 4 + 3) * GTJ + r] = make_float2(lv.w, xv.w);
        }
    }
    __syncthreads();

    unsigned long long dlx[4][4];
    #pragma unroll
    for (int a = 0; a < 4; a++)
        #pragma unroll
        for (int b = 0; b < 4; b++) dlx[a][b] = 0ull;

    const float4* pi4 = (const float4*)sPi + ty * 2;
    const float4* pj4 = (const float4*)sPj + tx * 2;

    #pragma unroll 4
    for (int c = 0; c < C; c++) {
        F4U pia, pib, pja, pjb;
        pia.f = pi4[c * (GTI / 2)];
        pib.f = pi4[c * (GTI / 2) + 1];
        pja.f = pj4[c * (GTJ / 2)];
        pjb.f = pj4[c * (GTJ / 2) + 1];
        unsigned long long pi[4] = {pia.u[0], pia.u[1], pib.u[0], pib.u[1]};
        unsigned long long pj[4] = {pja.u[0], pja.u[1], pjb.u[0], pjb.u[1]};
        #pragma unroll
        for (int ki = 0; ki < 4; ki++)
            #pragma unroll
            for (int kj = 0; kj < 4; kj++)
                dlx[ki][kj] = fma2(pi[ki], pj[kj], dlx[ki][kj]);
    }

    F4U nb, na;
    nb.f = *(const float4*)&g_nn[1][j0 + tx * 4];
    na.f = *(const float4*)&g_nn[0][i0 + ty * 4];

    #pragma unroll
    for (int ki = 0; ki < 4; ki++) {
        int i = i0 + ty * 4 + ki;
        F4U wv;
        int rcnt = 0;
        #pragma unroll
        for (int kj = 0; kj < 4; kj++) {
            float2 v = *(float2*)&dlx[ki][kj];           // (dl, dx)
            float d2 = fmaxf(na.s[ki] + nb.s[kj] - 2.0f * v.y, 1e-12f);
            float ed = sqrtf(d2) + 1e-10f;
            float hinge = fmaxf(MARGIN_F - ed, 0.0f);
            float w = hinge * (1.0f - v.x);
            wv.s[kj] = w;
            rcnt += (w > 0.0f) ? 1 : 0;
        }
        *(float4*)&g_w[i][j0 + tx * 4] = wv.f;
        #pragma unroll
        for (int off = 8; off; off >>= 1)
            rcnt += __shfl_down_sync(0xffffffffu, rcnt, off, 16);
        if (tx == 0) atomicAdd(&g_rowcnt[i], rcnt);
    }
}

// ---------------- kernel 3: js log-sums + folded finalize -----------------------
// 32i x 32j tile, 128 thr (8tx x 16ty), 2i x 4j micro-tile, 16 KB smem, low regs
// -> ~7 blocks/SM resident. Inner: LDS.64 + LDS.128 + 8x(FADD+MUFU.LG2+FFMA).
// js = Ka + Kb - 0.5ln2 * sum_c s*lg2(s). rsum += w*js.  Last block finalizes.
__global__ void __launch_bounds__(128)
js_kernel(const float* __restrict__ xp1, const float* __restrict__ xp2,
          float* __restrict__ out, int out_size) {
    __shared__ float sm[C * (JTI + JTJ)];   // 16 KB
    float* sA = sm;                          // [C][JTI]
    float* sB = sm + C * JTI;                // [C][JTJ]

    const int tx = threadIdx.x, ty = threadIdx.y;   // tx 0..7, ty 0..15
    const int tid = ty * 8 + tx;
    const int i0 = blockIdx.y * JTI, j0 = blockIdx.x * JTJ;

    {
        int r = tid & 31, c0 = tid >> 5;             // c0: 0..3
        #pragma unroll
        for (int p = 0; p < 4; p++) {
            int cb = c0 + 4 * p;                     // 0..15
            float4 u = *(const float4*)&xp1[(i0 + r) * C + cb * 4];
            float4 v = *(const float4*)&xp2[(j0 + r) * C + cb * 4];
            sA[(cb * 4 + 0) * JTI + r] = u.x + EPSJ;
            sA[(cb * 4 + 1) * JTI + r] = u.y + EPSJ;
            sA[(cb * 4 + 2) * JTI + r] = u.z + EPSJ;
            sA[(cb * 4 + 3) * JTI + r] = u.w + EPSJ;
            sB[(cb * 4 + 0) * JTJ + r] = v.x + EPSJ;
            sB[(cb * 4 + 1) * JTJ + r] = v.y + EPSJ;
            sB[(cb * 4 + 2) * JTJ + r] = v.z + EPSJ;
            sB[(cb * 4 + 3) * JTJ + r] = v.w + EPSJ;
        }
    }

    // prefetch pair weights (hides LDG latency behind the log loop)
    F4U w0, w1;
    w0.f = *(const float4*)&g_w[i0 + ty * 2 + 0][j0 + tx * 4];
    w1.f = *(const float4*)&g_w[i0 + ty * 2 + 1][j0 + tx * 4];
    float2 Ka = *(const float2*)&g_K[0][i0 + ty * 2];
    F4U Kb; Kb.f = *(const float4*)&g_K[1][j0 + tx * 4];

    __syncthreads();

    float jsum[2][4];
    #pragma unroll
    for (int a = 0; a < 2; a++)
        #pragma unroll
        for (int b = 0; b < 4; b++) jsum[a][b] = 0.0f;

    const float2* a2 = (const float2*)sA + ty;       // stride JTI/2=16 per c
    const float4* b4 = (const float4*)sB + tx;       // stride JTJ/4=8  per c

    #pragma unroll 8
    for (int c = 0; c < C; c++) {
        float2 av = a2[c * (JTI / 2)];
        F4U bv; bv.f = b4[c * (JTJ / 4)];
        float a[2] = {av.x, av.y};
        #pragma unroll
        for (int ki = 0; ki < 2; ki++)
            #pragma unroll
            for (int kj = 0; kj < 4; kj++) {
                float s = a[ki] + bv.s[kj];
                jsum[ki][kj] = fmaf(s, __log2f(s), jsum[ki][kj]);
            }
    }

    #pragma unroll
    for (int ki = 0; ki < 2; ki++) {
        int i = i0 + ty * 2 + ki;
        float Kai = (ki == 0) ? Ka.x : Ka.y;
        const F4U& wv = (ki == 0) ? w0 : w1;
        float rsum = 0.0f;
        #pragma unroll
        for (int kj = 0; kj < 4; kj++) {
            float js = Kai + Kb.s[kj] - HLN2 * jsum[ki][kj];
            rsum = fmaf(wv.s[kj], js, rsum);
        }
        #pragma unroll
        for (int off = 4; off; off >>= 1)
            rsum += __shfl_down_sync(0xffffffffu, rsum, off, 8);
        if (tx == 0) atomicAdd(&g_rowsum[i], rsum);
    }

    // ---- folded finalize: last block to finish reduces everything ----
    __threadfence();
    __syncthreads();
    __shared__ int s_last;
    if (tid == 0) s_last = atomicAdd(&g_done, 1);
    __syncthreads();
    if (s_last != NBLKJ - 1) return;

    float nega = 0.0f, posi = 0.0f, ood = 0.0f;
    for (int r = tid; r < NROWS; r += 128) {
        float rs = __ldcg(&g_rowsum[r]);
        int   rc = __ldcg(&g_rowcnt[r]);
        nega += rs / (float)(rc > 0 ? rc : 1);
    }
    for (int r = tid; r < 2 * NROWS; r += 128) {
        posi += g_pos[r];
        ood  += g_oodv[r];
    }
    float* red = sm;
    red[tid]       = nega;
    red[128 + tid] = posi;
    red[256 + tid] = ood;
    __syncthreads();
    for (int off = 64; off; off >>= 1) {
        if (tid < off) {
            red[tid]       += red[tid + off];
            red[128 + tid] += red[128 + tid + off];
            red[256 + tid] += red[256 + tid + off];
        }
        __syncthreads();
    }
    for (int r = 3 + tid; r < out_size; r += 128) out[r] = 0.0f;  // defensive
    if (tid == 0) {
        float ng = red[0];
        float ps = 0.5f * red[128];
        float od = 0.5f * red[256];
        if (out_size > 0) out[0] = ps + ng + 0.5f * od;   // LAM = 0.5
        if (out_size > 1) out[1] = ps;
        if (out_size > 2) out[2] = ng;
    }
}

// ---------------- launch ---------------------------------------------------------
extern "C" void kernel_launch(void* const* d_in, const int* in_sizes, int n_in,
                              void* d_out, int out_size) {
    const float* x1  = (const float*)d_in[0];
    const float* x2  = (const float*)d_in[1];
    const float* xp1 = (const float*)d_in[2];
    const float* xp2 = (const float*)d_in[3];
    const float* l1  = (const float*)d_in[4];
    const float* l2  = (const float*)d_in[5];
    float* out = (float*)d_out;

    row_kernel<<<256, 256>>>(x1, x2, xp1, xp2, l1, l2);

    const int gsmem = C * (GTI + GTJ) * (int)sizeof(float2);   // 49,152 B
    cudaFuncSetAttribute(gram_kernel, cudaFuncAttributeMaxDynamicSharedMemorySize,
                         gsmem);
    gram_kernel<<<dim3(NROWS / GTJ, NROWS / GTI), dim3(16, 8), gsmem>>>(x1, x2, l1, l2);

    js_kernel<<<dim3(NROWS / JTJ, NROWS / JTI), dim3(8, 16)>>>(xp1, xp2, out, out_size);
}

// round 9
// speedup vs baseline: 1.0367x; 1.0367x over previous
#include <cuda_runtime.h>
#include <math.h>

#define NROWS 1024
#define C 64
#define MARGIN_F 15.0f
#define EPSJ 1e-8f
#define HLN2 0.34657359027997264f   /* 0.5*ln2 */

/* gram kernel tiling */
#define GTI 32
#define GTJ 64
/* js kernel tiling */
#define JTI 32
#define JTJ 32
#define NBLKJ 1024                   /* (1024/JTI)*(1024/JTJ) */

// ---------------- scratch (static device globals; no allocation) ----------------
__device__ float g_K[2][NROWS];      // 0.5*Sa + 0.5*ln2*sumA  per row
__device__ float g_nn[2][NROWS];     // ||x||^2 per row
__device__ float g_pos[2 * NROWS];   // per-row positive-branch contribution
__device__ float g_oodv[2 * NROWS];  // per-row ood contribution (var*coffi)
__device__ float g_rowsum[NROWS];    // negative-branch per-row pair sums
__device__ int   g_rowcnt[NROWS];    // negative-branch per-row counts
__device__ int   g_done;             // js-kernel completion counter
__device__ float g_w[NROWS][NROWS];  // per-pair weight hinge*(1-dl)  (4 MB)

__device__ __forceinline__ unsigned long long fma2(unsigned long long a,
                                                   unsigned long long b,
                                                   unsigned long long c) {
    unsigned long long d;
    asm("fma.rn.f32x2 %0, %1, %2, %3;" : "=l"(d) : "l"(a), "l"(b), "l"(c));
    return d;
}

union F4U {
    float4 f;
    unsigned long long u[2];
    float s[4];
};

__device__ __forceinline__ float wsum(float v) {
    #pragma unroll
    for (int off = 16; off; off >>= 1) v += __shfl_xor_sync(0xffffffffu, v, off);
    return v;
}
__device__ __forceinline__ float wmin(float v) {
    #pragma unroll
    for (int off = 16; off; off >>= 1)
        v = fminf(v, __shfl_xor_sync(0xffffffffu, v, off));
    return v;
}

// ---------------- kernel 1: warp-per-row precompute + positive + ood ------------
__global__ void row_kernel(const float* __restrict__ x1, const float* __restrict__ x2,
                           const float* __restrict__ xp1, const float* __restrict__ xp2,
                           const float* __restrict__ l1,  const float* __restrict__ l2) {
    int gtid = blockIdx.x * blockDim.x + threadIdx.x;
    int w    = gtid >> 5;            // warp id: 0..2047
    int lane = gtid & 31;
    if (gtid == 0) g_done = 0;
    if (gtid < NROWS) { g_rowsum[gtid] = 0.0f; g_rowcnt[gtid] = 0; }

    int br = w >> 10;
    int i  = w & (NROWS - 1);
    const float* xr = (br ? x2  : x1)  + i * C;
    const float* pr = (br ? xp2 : xp1) + i * C;
    const float* lr = (br ? l2  : l1)  + i * C;

    float xv0 = xr[lane], xv1 = xr[lane + 32];
    float A0  = pr[lane] + EPSJ, A1 = pr[lane + 32] + EPSJ;
    float lv0 = lr[lane], lv1 = lr[lane + 32];

    float nn = wsum(fmaf(xv0, xv0, xv1 * xv1));

    float la0 = __logf(A0),                 la1 = __logf(A1);
    float L00 = __logf(0.5f * (A0 + EPSJ)), L01 = __logf(0.5f * (A1 + EPSJ));
    float L10 = __logf(0.5f * (A0 + 1.0f)), L11 = __logf(0.5f * (A1 + 1.0f));
    float P  = fmaf(A0, la0 - L00, A1 * (la1 - L01));
    float T  = L00 + L01;
    float Sa = fmaf(A0, la0, A1 * la1);
    float sA = A0 + A1;

    float pd0 = sqrtf(fmaxf(nn - 2.0f * xv0 + 1.0f, 1e-12f));
    float pd1 = sqrtf(fmaxf(nn - 2.0f * xv1 + 1.0f, 1e-12f));
    float h0  = -0.5f * A0 * (L00 - L10) - 0.5f * EPSJ * L00 + 0.5f * L10;
    float h1  = -0.5f * A1 * (L01 - L11) - 0.5f * EPSJ * L01 + 0.5f * L11;
    float w0  = pd0 * lv0, w1 = pd1 * lv1;
    float S1  = w0 + w1;
    float S2  = fmaf(w0, h0, w1 * h1);
    float r0  = fmaxf(MARGIN_F - pd0, 0.0f) * (1.0f / MARGIN_F);
    float r1  = fmaxf(MARGIN_F - pd1, 0.0f) * (1.0f / MARGIN_F);
    float var = fmaf(r0, r0, r1 * r1);
    float mn  = fminf(1.0f - r0, 1.0f - r1);

    P = wsum(P); T = wsum(T); Sa = wsum(Sa); sA = wsum(sA);
    S1 = wsum(S1); S2 = wsum(S2); var = wsum(var); mn = wmin(mn);

    if (lane == 0) {
        const float LOGEPS = -18.420680743952367f;   // ln(1e-8)
        float G = 1.0f - 0.5f * P - 0.5f * EPSJ * (float)(C - 1) * LOGEPS
                       + 0.5f * EPSJ * T;
        g_pos [w]   = G * S1 + S2;
        g_oodv[w]   = var * mn;
        g_K [br][i] = 0.5f * Sa + HLN2 * sA;
        g_nn[br][i] = nn;
    }
}

// ---------------- kernel 2: gram + weights --------------------------------------
// 32i x 64j tile, 128 thr (16tx x 8ty), 4i x 4j micro-tile.
// dl/dx via packed f32x2 FMA; w = hinge*(1-dl) -> g_w (float4 STG, coalesced);
// per-row counts via width-16 shuffle + atomics (w>0 <=> pairs>0, js>0 strictly).
__global__ void __launch_bounds__(128, 4)
gram_kernel(const float* __restrict__ x1, const float* __restrict__ x2,
            const float* __restrict__ l1,  const float* __restrict__ l2) {
    extern __shared__ float sm[];
    float2* sPi = (float2*)sm;            // [C][GTI] (l1,x1)  16 KB
    float2* sPj = sPi + C * GTI;          // [C][GTJ] (l2,x2)  32 KB

    const int tx = threadIdx.x, ty = threadIdx.y;
    const int tid = ty * 16 + tx;
    const int i0 = blockIdx.y * GTI, j0 = blockIdx.x * GTJ;

    {
        int r = tid & 31, c0 = tid >> 5;          // c0: 0..3
        #pragma unroll
        for (int p = 0; p < 4; p++) {
            int cb = c0 + 4 * p;
            float4 lv = *(const float4*)&l1[(i0 + r) * C + cb * 4];
            float4 xv = *(const float4*)&x1[(i0 + r) * C + cb * 4];
            sPi[(cb * 4 + 0) * GTI + r] = make_float2(lv.x, xv.x);
            sPi[(cb * 4 + 1) * GTI + r] = make_float2(lv.y, xv.y);
            sPi[(cb * 4 + 2) * GTI + r] = make_float2(lv.z, xv.z);
            sPi[(cb * 4 + 3) * GTI + r] = make_float2(lv.w, xv.w);
        }
    }
    {
        int r = tid & 63, c0 = tid >> 6;          // c0: 0..1
        #pragma unroll
        for (int p = 0; p < 8; p++) {
            int cb = c0 + 2 * p;
            float4 lv = *(const float4*)&l2[(j0 + r) * C + cb * 4];
            float4 xv = *(const float4*)&x2[(j0 + r) * C + cb * 4];
            sPj[(cb * 4 + 0) * GTJ + r] = make_float2(lv.x, xv.x);
            sPj[(cb * 4 + 1) * GTJ + r] = make_float2(lv.y, xv.y);
            sPj[(cb * 4 + 2) * GTJ + r] = make_float2(lv.z, xv.z);
            sPj[(cb * 4 + 3) * GTJ + r] = make_float2(lv.w, xv.w);
        }
    }
    __syncthreads();

    unsigned long long dlx[4][4];
    #pragma unroll
    for (int a = 0; a < 4; a++)
        #pragma unroll
        for (int b = 0; b < 4; b++) dlx[a][b] = 0ull;

    const float4* pi4 = (const float4*)sPi + ty * 2;
    const float4* pj4 = (const float4*)sPj + tx * 2;

    #pragma unroll 4
    for (int c = 0; c < C; c++) {
        F4U pia, pib, pja, pjb;
        pia.f = pi4[c * (GTI / 2)];
        pib.f = pi4[c * (GTI / 2) + 1];
        pja.f = pj4[c * (GTJ / 2)];
        pjb.f = pj4[c * (GTJ / 2) + 1];
        unsigned long long pi[4] = {pia.u[0], pia.u[1], pib.u[0], pib.u[1]};
        unsigned long long pj[4] = {pja.u[0], pja.u[1], pjb.u[0], pjb.u[1]};
        #pragma unroll
        for (int ki = 0; ki < 4; ki++)
            #pragma unroll
            for (int kj = 0; kj < 4; kj++)
                dlx[ki][kj] = fma2(pi[ki], pj[kj], dlx[ki][kj]);
    }

    F4U nb, na;
    nb.f = *(const float4*)&g_nn[1][j0 + tx * 4];
    na.f = *(const float4*)&g_nn[0][i0 + ty * 4];

    #pragma unroll
    for (int ki = 0; ki < 4; ki++) {
        int i = i0 + ty * 4 + ki;
        F4U wv;
        int rcnt = 0;
        #pragma unroll
        for (int kj = 0; kj < 4; kj++) {
            float2 v = *(float2*)&dlx[ki][kj];           // (dl, dx)
            float d2 = fmaxf(na.s[ki] + nb.s[kj] - 2.0f * v.y, 1e-12f);
            float ed = sqrtf(d2) + 1e-10f;
            float hinge = fmaxf(MARGIN_F - ed, 0.0f);
            float w = hinge * (1.0f - v.x);
            wv.s[kj] = w;
            rcnt += (w > 0.0f) ? 1 : 0;
        }
        *(float4*)&g_w[i][j0 + tx * 4] = wv.f;
        #pragma unroll
        for (int off = 8; off; off >>= 1)
            rcnt += __shfl_down_sync(0xffffffffu, rcnt, off, 16);
        if (tx == 0) atomicAdd(&g_rowcnt[i], rcnt);
    }
}

// ---------------- kernel 3: js log-sums + folded finalize -----------------------
// 32i x 32j tile, 128 thr (8tx x 16ty), 2i x 4j micro-tile, 16 KB smem.
// __launch_bounds__(128, 8): forces regs <= 64 so 8 blocks/SM are resident ->
// all 1024 blocks in one wave, ~7 warps/SMSP hiding MUFU latency.
// Inner: LDS.64 + LDS.128 + 8x(FADD + MUFU.LG2 + FFMA).
// js = Ka + Kb - 0.5ln2 * sum_c s*lg2(s). rsum += w*js. Last block finalizes.
__global__ void __launch_bounds__(128, 8)
js_kernel(const float* __restrict__ xp1, const float* __restrict__ xp2,
          float* __restrict__ out, int out_size) {
    __shared__ float sm[C * (JTI + JTJ)];   // 16 KB
    float* sA = sm;                          // [C][JTI]
    float* sB = sm + C * JTI;                // [C][JTJ]

    const int tx = threadIdx.x, ty = threadIdx.y;   // tx 0..7, ty 0..15
    const int tid = ty * 8 + tx;
    const int i0 = blockIdx.y * JTI, j0 = blockIdx.x * JTJ;

    {
        int r = tid & 31, c0 = tid >> 5;             // c0: 0..3
        #pragma unroll
        for (int p = 0; p < 4; p++) {
            int cb = c0 + 4 * p;                     // 0..15
            float4 u = *(const float4*)&xp1[(i0 + r) * C + cb * 4];
            float4 v = *(const float4*)&xp2[(j0 + r) * C + cb * 4];
            sA[(cb * 4 + 0) * JTI + r] = u.x + EPSJ;
            sA[(cb * 4 + 1) * JTI + r] = u.y + EPSJ;
            sA[(cb * 4 + 2) * JTI + r] = u.z + EPSJ;
            sA[(cb * 4 + 3) * JTI + r] = u.w + EPSJ;
            sB[(cb * 4 + 0) * JTJ + r] = v.x + EPSJ;
            sB[(cb * 4 + 1) * JTJ + r] = v.y + EPSJ;
            sB[(cb * 4 + 2) * JTJ + r] = v.z + EPSJ;
            sB[(cb * 4 + 3) * JTJ + r] = v.w + EPSJ;
        }
    }

    // prefetch pair weights / constants (hides LDG latency behind the log loop)
    F4U w0, w1;
    w0.f = __ldg((const float4*)&g_w[i0 + ty * 2 + 0][j0 + tx * 4]);
    w1.f = __ldg((const float4*)&g_w[i0 + ty * 2 + 1][j0 + tx * 4]);
    float2 Ka = __ldg((const float2*)&g_K[0][i0 + ty * 2]);
    F4U Kb; Kb.f = __ldg((const float4*)&g_K[1][j0 + tx * 4]);

    __syncthreads();

    float jsum[2][4];
    #pragma unroll
    for (int a = 0; a < 2; a++)
        #pragma unroll
        for (int b = 0; b < 4; b++) jsum[a][b] = 0.0f;

    const float2* a2 = (const float2*)sA + ty;       // stride JTI/2=16 per c
    const float4* b4 = (const float4*)sB + tx;       // stride JTJ/4=8  per c

    #pragma unroll 8
    for (int c = 0; c < C; c++) {
        float2 av = a2[c * (JTI / 2)];
        F4U bv; bv.f = b4[c * (JTJ / 4)];
        float a[2] = {av.x, av.y};
        #pragma unroll
        for (int ki = 0; ki < 2; ki++)
            #pragma unroll
            for (int kj = 0; kj < 4; kj++) {
                float s = a[ki] + bv.s[kj];
                jsum[ki][kj] = fmaf(s, __log2f(s), jsum[ki][kj]);
            }
    }

    #pragma unroll
    for (int ki = 0; ki < 2; ki++) {
        int i = i0 + ty * 2 + ki;
        float Kai = (ki == 0) ? Ka.x : Ka.y;
        const F4U& wv = (ki == 0) ? w0 : w1;
        float rsum = 0.0f;
        #pragma unroll
        for (int kj = 0; kj < 4; kj++) {
            float js = Kai + Kb.s[kj] - HLN2 * jsum[ki][kj];
            rsum = fmaf(wv.s[kj], js, rsum);
        }
        #pragma unroll
        for (int off = 4; off; off >>= 1)
            rsum += __shfl_down_sync(0xffffffffu, rsum, off, 8);
        if (tx == 0) atomicAdd(&g_rowsum[i], rsum);
    }

    // ---- folded finalize: last block to finish reduces everything ----
    __threadfence();
    __syncthreads();
    __shared__ int s_last;
    if (tid == 0) s_last = atomicAdd(&g_done, 1);
    __syncthreads();
    if (s_last != NBLKJ - 1) return;

    float nega = 0.0f, posi = 0.0f, ood = 0.0f;
    for (int r = tid; r < NROWS; r += 128) {
        float rs = __ldcg(&g_rowsum[r]);
        int   rc = __ldcg(&g_rowcnt[r]);
        nega += rs / (float)(rc > 0 ? rc : 1);
    }
    for (int r = tid; r < 2 * NROWS; r += 128) {
        posi += g_pos[r];
        ood  += g_oodv[r];
    }
    float* red = sm;
    red[tid]       = nega;
    red[128 + tid] = posi;
    red[256 + tid] = ood;
    __syncthreads();
    for (int off = 64; off; off >>= 1) {
        if (tid < off) {
            red[tid]       += red[tid + off];
            red[128 + tid] += red[128 + tid + off];
            red[256 + tid] += red[256 + tid + off];
        }
        __syncthreads();
    }
    for (int r = 3 + tid; r < out_size; r += 128) out[r] = 0.0f;  // defensive
    if (tid == 0) {
        float ng = red[0];
        float ps = 0.5f * red[128];
        float od = 0.5f * red[256];
        if (out_size > 0) out[0] = ps + ng + 0.5f * od;   // LAM = 0.5
        if (out_size > 1) out[1] = ps;
        if (out_size > 2) out[2] = ng;
    }
}

// ---------------- launch ---------------------------------------------------------
extern "C" void kernel_launch(void* const* d_in, const int* in_sizes, int n_in,
                              void* d_out, int out_size) {
    const float* x1  = (const float*)d_in[0];
    const float* x2  = (const float*)d_in[1];
    const float* xp1 = (const float*)d_in[2];
    const float* xp2 = (const float*)d_in[3];
    const float* l1  = (const float*)d_in[4];
    const float* l2  = (const float*)d_in[5];
    float* out = (float*)d_out;

    row_kernel<<<256, 256>>>(x1, x2, xp1, xp2, l1, l2);

    const int gsmem = C * (GTI + GTJ) * (int)sizeof(float2);   // 49,152 B
    cudaFuncSetAttribute(gram_kernel, cudaFuncAttributeMaxDynamicSharedMemorySize,
                         gsmem);
    gram_kernel<<<dim3(NROWS / GTJ, NROWS / GTI), dim3(16, 8), gsmem>>>(x1, x2, l1, l2);

    js_kernel<<<dim3(NROWS / JTJ, NROWS / JTI), dim3(8, 16)>>>(xp1, xp2, out, out_size);
}